// round 1
// baseline (speedup 1.0000x reference)
#include <cuda_runtime.h>
#include <math.h>
#include <stdint.h>

#define BATCH 128
#define CH    320
#define HW    256
#define NB    3
#define NGRP  5
#define CPG   64
#define IMG_TOT (BATCH*CH)            /* 40960 rows */

static __device__ float g_ReK[NB*256];
static __device__ float g_AT [NB*256*256];
static __device__ float g_avg[IMG_TOT];
static __device__ float g_cw [BATCH*3*CH];
static __device__ float g_Y   [(size_t)NB*IMG_TOT*HW];   /* band features  */
static __device__ float g_CONV[(size_t)NB*IMG_TOT*HW];   /* conv outputs   */
static __device__ float g_mu [NB*BATCH*NGRP];
static __device__ float g_rs [NB*BATCH*NGRP];
static __device__ float g_fused[(size_t)IMG_TOT*HW];

__device__ __forceinline__ float sigf(float z) { return 1.0f/(1.0f+expf(-z)); }

/* ---------------- Kernel 1: masks (bit-exact vs JAX) + band kernels ReK ------- */
__global__ void k_prep(const float* lcp, const float* hcp)
{
    __shared__ float msk[3][256];
    __shared__ float ct[16];
    int tid = threadIdx.x;
    if (tid < 16) ct[tid] = (float)cos((double)tid * (3.141592653589793/8.0));
    float lc = *lcp, hc = *hcp;
    int i = tid >> 4, j = tid & 15;
    /* linspace(-1,1,16): g = i*(2/15) + (-1), separate f32 roundings (no FMA) */
    float step = __fdiv_rn(2.0f, 15.0f);
    float gi = __fadd_rn(__fmul_rn((float)i, step), -1.0f);
    float gj = __fadd_rn(__fmul_rn((float)j, step), -1.0f);
    if (i == 15) gi = 1.0f;   /* numpy/jnp linspace pins the endpoint */
    if (j == 15) gj = 1.0f;
    float d2   = __fadd_rn(__fmul_rn(gj,gj), __fmul_rn(gi,gi));
    float dist = __fdiv_rn(__fsqrt_rn(d2), 1.41421356237309515f);
    float ml = sigf(__fdiv_rn(__fsub_rn(lc,  dist), 1e-6f));
    float mm = sigf(__fdiv_rn(__fsub_rn(dist, lc ), 1e-6f)) *
               sigf(__fdiv_rn(__fsub_rn(hc,  dist), 1e-6f));
    float mh = sigf(__fdiv_rn(__fsub_rn(dist, hc ), 1e-6f));
    msk[0][tid] = ml; msk[1][tid] = mm; msk[2][tid] = mh;
    __syncthreads();
    /* ReK[a,b] = (1/256) * sum_{i,j} mask[i][j] * cos(2*pi*((i+8)*a+(j+8)*b)/16) */
    double a0 = 0.0, a1 = 0.0, a2 = 0.0;
    for (int ii = 0; ii < 16; ii++)
        for (int jj = 0; jj < 16; jj++) {
            float cv = ct[(((ii+8)*i + (jj+8)*j) & 15)];
            int m = ii*16 + jj;
            a0 += (double)(msk[0][m]*cv);
            a1 += (double)(msk[1][m]*cv);
            a2 += (double)(msk[2][m]*cv);
        }
    g_ReK[0*256+tid] = (float)(a0*(1.0/256.0));
    g_ReK[1*256+tid] = (float)(a1*(1.0/256.0));
    g_ReK[2*256+tid] = (float)(a2*(1.0/256.0));
}

/* ---------------- Kernel 2: circulant matrix AT[q][a] = ReK[a-q] -------------- */
__global__ void k_at()
{
    int q = blockIdx.x, band = blockIdx.y, a = threadIdx.x;
    int qr = q >> 4, qc = q & 15, ar = a >> 4, ac = a & 15;
    g_AT[((band << 8) + q)*256 + a] =
        g_ReK[(band << 8) + (((ar - qr) & 15) << 4) + ((ac - qc) & 15)];
}

/* ---------------- Kernel 3: per-(b,c) mean over 256 -------------------------- */
__global__ void k_avg(const float* __restrict__ x)
{
    int w = blockIdx.x*8 + (threadIdx.x >> 5);
    int lane = threadIdx.x & 31;
    const float* p = x + (size_t)w*HW;
    float s = 0.f;
    #pragma unroll
    for (int k = lane; k < HW; k += 32) s += p[k];
    #pragma unroll
    for (int o = 16; o; o >>= 1) s += __shfl_xor_sync(0xffffffffu, s, o);
    if (lane == 0) g_avg[w] = s * (1.0f/256.0f);
}

/* ---------------- Kernel 4: channel-attention MLP ---------------------------- */
__global__ void k_ca(const float* __restrict__ w1, const float* __restrict__ b1,
                     const float* __restrict__ w2, const float* __restrict__ b2)
{
    __shared__ float av[CH];
    __shared__ float h[40];
    int b = blockIdx.x, tid = threadIdx.x;
    for (int k = tid; k < CH; k += 256) av[k] = g_avg[b*CH + k];
    __syncthreads();
    if (tid < 40) {
        float s = 0.f;
        const float* w = w1 + tid*CH;
        for (int k = 0; k < CH; k++) s = fmaf(av[k], w[k], s);
        h[tid] = fmaxf(s + b1[tid], 0.f);
    }
    __syncthreads();
    for (int j = tid; j < 3*CH; j += 256) {
        float s = 0.f;
        const float* w = w2 + j*40;
        #pragma unroll
        for (int k = 0; k < 40; k++) s = fmaf(h[k], w[k], s);
        g_cw[b*3*CH + j] = sigf(s + b2[j]);
    }
}

/* ---------------- Kernel 5: band transform  Y = X * AT ----------------------- */
__global__ void __launch_bounds__(256, 2) k_band(const float* __restrict__ x)
{
    int band = blockIdx.y;
    int r0   = blockIdx.x * 64;
    __shared__ __align__(16) float Xs[64][64];
    int tid = threadIdx.x;
    const float* ATb = g_AT + (size_t)band*65536 + tid;
    float acc[64];
    #pragma unroll
    for (int k = 0; k < 64; k++) acc[k] = 0.f;

    for (int q0 = 0; q0 < 256; q0 += 64) {
        __syncthreads();
        #pragma unroll
        for (int k = 0; k < 16; k++) {
            int idx = tid + k*256;
            int rr = idx >> 6, qq = idx & 63;
            Xs[rr][qq] = x[(size_t)(r0+rr)*HW + q0 + qq];
        }
        __syncthreads();
        #pragma unroll 1
        for (int qb = 0; qb < 16; qb++) {
            const float* atp = ATb + (size_t)(q0 + 4*qb)*256;
            float at0 = atp[0], at1 = atp[256], at2 = atp[512], at3 = atp[768];
            #pragma unroll
            for (int r = 0; r < 64; r++) {
                float4 xv = *(const float4*)&Xs[r][4*qb];
                acc[r] = fmaf(xv.x, at0, acc[r]);
                acc[r] = fmaf(xv.y, at1, acc[r]);
                acc[r] = fmaf(xv.z, at2, acc[r]);
                acc[r] = fmaf(xv.w, at3, acc[r]);
            }
        }
    }
    float* out = g_Y + (size_t)band*IMG_TOT*HW + (size_t)r0*HW + tid;
    #pragma unroll
    for (int r = 0; r < 64; r++) out[(size_t)r*HW] = acc[r];
}

/* ---------------- Kernel 6: 3x3 conv (SAME, zero pad) + bias ----------------- */
__global__ void __launch_bounds__(256, 2) k_conv(
    const float* __restrict__ wlow, const float* __restrict__ wmid, const float* __restrict__ whigh,
    const float* __restrict__ blow, const float* __restrict__ bmid, const float* __restrict__ bhigh)
{
    int band = blockIdx.z, b = blockIdx.y, co0 = blockIdx.x*64;
    const float* W    = (band == 0) ? wlow : (band == 1) ? wmid : whigh;
    const float* bias = (band == 0) ? blow : (band == 1) ? bmid : bhigh;

    __shared__ float Yp[18][19];
    __shared__ __align__(16) float Ws[9][64];
    __shared__ float bsm[64];
    int tid = threadIdx.x;
    if (tid < 64) bsm[tid] = bias[co0 + tid];

    const float* Yimg = g_Y + ((size_t)band*IMG_TOT + (size_t)b*CH)*HW;
    int r = tid >> 4, c = tid & 15;

    float acc[64];
    #pragma unroll
    for (int k = 0; k < 64; k++) acc[k] = 0.f;

    #pragma unroll 1
    for (int ci = 0; ci < CH; ci++) {
        __syncthreads();
        for (int k = tid; k < 18*19; k += 256) {
            int rr = k/19, cc = k - rr*19;
            float v = 0.f;
            if (rr >= 1 && rr <= 16 && cc >= 1 && cc <= 16)
                v = Yimg[(size_t)ci*HW + (rr-1)*16 + (cc-1)];
            Yp[rr][cc] = v;
        }
        for (int k = tid; k < 576; k += 256) {
            int co = k/9, t = k - co*9;
            Ws[t][co] = W[(size_t)(co0+co)*2880 + ci*9 + t];
        }
        __syncthreads();
        float yv[9];
        #pragma unroll
        for (int dr = 0; dr < 3; dr++)
            #pragma unroll
            for (int dc = 0; dc < 3; dc++)
                yv[dr*3+dc] = Yp[r+dr][c+dc];
        #pragma unroll
        for (int t = 0; t < 9; t++) {
            float y = yv[t];
            const float4* w4 = (const float4*)Ws[t];
            #pragma unroll
            for (int j = 0; j < 16; j++) {
                float4 wv = w4[j];
                acc[4*j+0] = fmaf(wv.x, y, acc[4*j+0]);
                acc[4*j+1] = fmaf(wv.y, y, acc[4*j+1]);
                acc[4*j+2] = fmaf(wv.z, y, acc[4*j+2]);
                acc[4*j+3] = fmaf(wv.w, y, acc[4*j+3]);
            }
        }
    }
    float* out = g_CONV + ((size_t)band*IMG_TOT + (size_t)b*CH + co0)*HW;
    #pragma unroll
    for (int k = 0; k < 64; k++) out[(size_t)k*HW + tid] = acc[k] + bsm[k];
}

/* ---------------- Kernel 7: GroupNorm statistics ----------------------------- */
__global__ void k_gn()
{
    int grp = blockIdx.x, b = blockIdx.y, band = blockIdx.z;
    const float* p = g_CONV + (((size_t)band*BATCH + b)*CH + grp*CPG)*HW;
    float s = 0.f, s2 = 0.f;
    for (int k = threadIdx.x; k < CPG*HW; k += 256) {
        float v = p[k];
        s += v; s2 = fmaf(v, v, s2);
    }
    __shared__ float sh[8], sh2[8];
    int lane = threadIdx.x & 31, wid = threadIdx.x >> 5;
    #pragma unroll
    for (int o = 16; o; o >>= 1) {
        s  += __shfl_xor_sync(0xffffffffu, s,  o);
        s2 += __shfl_xor_sync(0xffffffffu, s2, o);
    }
    if (lane == 0) { sh[wid] = s; sh2[wid] = s2; }
    __syncthreads();
    if (threadIdx.x == 0) {
        float ts = 0.f, ts2 = 0.f;
        #pragma unroll
        for (int k = 0; k < 8; k++) { ts += sh[k]; ts2 += sh2[k]; }
        float mu  = ts * (1.0f/16384.0f);
        float var = ts2 * (1.0f/16384.0f) - mu*mu;
        int idx = (band*BATCH + b)*NGRP + grp;
        g_mu[idx] = mu;
        g_rs[idx] = rsqrtf(var + 1e-5f);
    }
}

/* ---------------- Kernel 8: GN apply + residual + fuse + spatial attn -------- */
__global__ void k_fuse(const float* __restrict__ x,
                       const float* __restrict__ saw_g, const float* __restrict__ sab_g,
                       const float* __restrict__ lg, const float* __restrict__ lb,
                       const float* __restrict__ mg, const float* __restrict__ mb,
                       const float* __restrict__ hg, const float* __restrict__ hb,
                       float* __restrict__ out)
{
    __shared__ float cw0[CH], cw1[CH], cw2[CH];
    __shared__ float gL[CH], bL[CH], gM[CH], bM[CH], gH[CH], bH[CH], saw[CH];
    __shared__ float mus[15], rss[15];
    int b = blockIdx.x, tid = threadIdx.x;
    for (int k = tid; k < CH; k += 256) {
        cw0[k] = g_cw[b*3*CH + k];
        cw1[k] = g_cw[b*3*CH + CH + k];
        cw2[k] = g_cw[b*3*CH + 2*CH + k];
        gL[k] = lg[k]; bL[k] = lb[k];
        gM[k] = mg[k]; bM[k] = mb[k];
        gH[k] = hg[k]; bH[k] = hb[k];
        saw[k] = saw_g[k];
    }
    if (tid < 15) {
        int band = tid/5, grp = tid - band*5;
        mus[tid] = g_mu[(band*BATCH + b)*NGRP + grp];
        rss[tid] = g_rs[(band*BATCH + b)*NGRP + grp];
    }
    float sab = sab_g[0];
    __syncthreads();

    const size_t BSZ = (size_t)IMG_TOT*HW;
    int p = tid;
    float swacc = 0.f;
    for (int c = 0; c < CH; c++) {
        size_t ix = ((size_t)b*CH + c)*HW + p;
        float xv = x[ix];
        int grp = c >> 6;
        float vl = g_CONV[ix];
        float vm = g_CONV[BSZ + ix];
        float vh = g_CONV[2*BSZ + ix];
        float fl = (vl - mus[grp     ])*rss[grp     ]*gL[c] + bL[c] + xv;
        float fm = (vm - mus[5  + grp])*rss[5  + grp]*gM[c] + bM[c] + xv;
        float fh = (vh - mus[10 + grp])*rss[10 + grp]*gH[c] + bH[c] + xv;
        float fu = cw0[c]*fl + cw1[c]*fm + cw2[c]*fh;
        g_fused[ix] = fu;
        swacc = fmaf(fu, saw[c], swacc);
    }
    float sw = sigf(swacc + sab);
    for (int c = 0; c < CH; c++) {
        size_t ix = ((size_t)b*CH + c)*HW + p;
        out[ix] = g_fused[ix] * sw;
    }
}

/* ---------------- launch ------------------------------------------------------ */
extern "C" void kernel_launch(void* const* d_in, const int* in_sizes, int n_in,
                              void* d_out, int out_size)
{
    const float* x      = (const float*)d_in[0];
    const float* lc     = (const float*)d_in[1];
    const float* hc     = (const float*)d_in[2];
    const float* ca_w1  = (const float*)d_in[3];
    const float* ca_b1  = (const float*)d_in[4];
    const float* ca_w2  = (const float*)d_in[5];
    const float* ca_b2  = (const float*)d_in[6];
    const float* low_w  = (const float*)d_in[7];
    const float* low_b  = (const float*)d_in[8];
    const float* low_g  = (const float*)d_in[9];
    const float* low_be = (const float*)d_in[10];
    const float* mid_w  = (const float*)d_in[11];
    const float* mid_b  = (const float*)d_in[12];
    const float* mid_g  = (const float*)d_in[13];
    const float* mid_be = (const float*)d_in[14];
    const float* high_w = (const float*)d_in[15];
    const float* high_b = (const float*)d_in[16];
    const float* high_g = (const float*)d_in[17];
    const float* high_be= (const float*)d_in[18];
    const float* sa_w   = (const float*)d_in[19];
    const float* sa_b   = (const float*)d_in[20];
    float* out = (float*)d_out;

    k_prep<<<1, 256>>>(lc, hc);
    k_at  <<<dim3(256, NB), 256>>>();
    k_avg <<<IMG_TOT/8, 256>>>(x);
    k_ca  <<<BATCH, 256>>>(ca_w1, ca_b1, ca_w2, ca_b2);
    k_band<<<dim3(IMG_TOT/64, NB), 256>>>(x);
    k_conv<<<dim3(CH/64, BATCH, NB), 256>>>(low_w, mid_w, high_w, low_b, mid_b, high_b);
    k_gn  <<<dim3(NGRP, BATCH, NB), 256>>>();
    k_fuse<<<BATCH, 256>>>(x, sa_w, sa_b, low_g, low_be, mid_g, mid_be, high_g, high_be, out);
}